// round 12
// baseline (speedup 1.0000x reference)
#include <cuda_runtime.h>

// LSTM, batch=1, H=4, T=2^20, float32.
// Chunked time-parallel scan exploiting exponential state contraction.
// R11: re-tiled SIMT mapping — 2 lanes per chunk (16 chunks per warp).
//   Lane p of a pair owns output elements {2p, 2p+1} (8 gate rows). Partner
//   h values arrive via 2 width-2 shfl.bfly. One warp-step advances 16
//   chunks with ~93 instructions (vs 8 chunks / ~73 before): 1.6x fewer
//   total warp-instructions.
//   i/f/o rows prescaled by 0.5 (sigmoid = MUFU.TANH + FFMA); g row exact.
//   PF=4 prefetch with 4x-unrolled clean loops (rotation = renaming);
//   block 0 / last block take masked-clamped paths.
// CL=32, WU=32, 65536 threads / 2048 warps / 1024 blocks.

#define T_LEN   1048576
#define CL      32
#define WU      32
#define NCHUNK  (T_LEN / CL)        // 32768
#define NTHREADS (NCHUNK * 2)       // 65536
#define BLOCK   64
#define PF      4                   // prefetch depth == unroll factor

__device__ __forceinline__ float tanh_mufu(float z) {
    float r;
    asm("tanh.approx.f32 %0, %1;" : "=f"(r) : "f"(z));
    return r;
}
// width-2 butterfly shuffle (xor 1), bare SHFL.BFLY
__device__ __forceinline__ float shfl_bfly2(float v) {
    float r;
    asm("shfl.sync.bfly.b32 %0, %1, 1, 0x1e1f, 0xffffffff;" : "=f"(r) : "f"(v));
    return r;
}

__global__ void __launch_bounds__(BLOCK, 7)
lstm_chunked_scan(const float4* __restrict__ x,      // [T] of float4 (H=4)
                  const float*  __restrict__ Wih,    // [16][4]
                  const float*  __restrict__ Whh,    // [16][4]
                  const float*  __restrict__ bih,    // [16]
                  const float*  __restrict__ bhh,    // [16]
                  const float*  __restrict__ h0v,    // [4]
                  const float*  __restrict__ c0v,    // [4]
                  float*        __restrict__ out)    // [T][4]
{
    const int tid = blockIdx.x * BLOCK + threadIdx.x;
    const int g   = tid >> 1;        // chunk id
    const int p   = tid & 1;         // half: owns elements 2p, 2p+1
    const int e0  = 2 * p,     e1 = 2 * p + 1;   // owned elements
    const int q0  = 2 - 2 * p, q1 = 3 - 2 * p;   // partner elements

    // Per-lane weights for 8 gate rows (2 elements x 4 gates).
    // wh[ee][m][0..3] multiplies {hA(own e0), hB(own e1), vA(partner e0'),
    // vB(partner e1')} respectively — columns permuted at load time.
    float wx[2][4][4], wh[2][4][4], bz[2][4];
    #pragma unroll
    for (int ee = 0; ee < 2; ee++) {
        const int e = 2 * p + ee;
        #pragma unroll
        for (int m = 0; m < 4; m++) {
            const int r = e + 4 * m;
            const float sc = (m == 2) ? 1.0f : 0.5f;
            #pragma unroll
            for (int k = 0; k < 4; k++)
                wx[ee][m][k] = sc * __ldg(&Wih[r * 4 + k]);
            wh[ee][m][0] = sc * __ldg(&Whh[r * 4 + e0]);
            wh[ee][m][1] = sc * __ldg(&Whh[r * 4 + e1]);
            wh[ee][m][2] = sc * __ldg(&Whh[r * 4 + q0]);
            wh[ee][m][3] = sc * __ldg(&Whh[r * 4 + q1]);
            bz[ee][m] = sc * (__ldg(&bih[r]) + __ldg(&bhh[r]));
        }
    }

    const int outStart = g * CL;
    const int t0 = outStart - WU;          // negative only inside block 0

    float hA = __ldg(&h0v[e0]), hB = __ldg(&h0v[e1]);
    float cA = __ldg(&c0v[e0]), cB = __ldg(&c0v[e1]);

    // Depth-4 x prefetch pipeline (low-clamped; only block 0 is negative)
    int i0 = t0     < 0 ? 0 : t0;
    int i1 = t0 + 1 < 0 ? 0 : t0 + 1;
    int i2 = t0 + 2 < 0 ? 0 : t0 + 2;
    int i3 = t0 + 3 < 0 ? 0 : t0 + 3;
    float4 x0 = __ldg(&x[i0]);
    float4 x1 = __ldg(&x[i1]);
    float4 x2 = __ldg(&x[i2]);
    float4 x3 = __ldg(&x[i3]);

    // One LSTM step for both owned elements. Partner-h terms fold last
    // (post-shfl depth 2 FMA).
#define STEP(XT, CNA, HNA, CNB, HNB)                                      \
    const float vA = shfl_bfly2(hA);                                      \
    const float vB = shfl_bfly2(hB);                                      \
    float z0[4], z1[4];                                                   \
    _Pragma("unroll")                                                     \
    for (int m = 0; m < 4; m++) {                                         \
        float a = fmaf(wx[0][m][0], (XT).x, bz[0][m]);                    \
        a = fmaf(wx[0][m][1], (XT).y, a);                                 \
        a = fmaf(wx[0][m][2], (XT).z, a);                                 \
        a = fmaf(wx[0][m][3], (XT).w, a);                                 \
        a = fmaf(wh[0][m][0], hA, a);                                     \
        a = fmaf(wh[0][m][1], hB, a);                                     \
        a = fmaf(wh[0][m][2], vA, a);                                     \
        z0[m] = fmaf(wh[0][m][3], vB, a);                                 \
        float b = fmaf(wx[1][m][0], (XT).x, bz[1][m]);                    \
        b = fmaf(wx[1][m][1], (XT).y, b);                                 \
        b = fmaf(wx[1][m][2], (XT).z, b);                                 \
        b = fmaf(wx[1][m][3], (XT).w, b);                                 \
        b = fmaf(wh[1][m][0], hA, b);                                     \
        b = fmaf(wh[1][m][1], hB, b);                                     \
        b = fmaf(wh[1][m][2], vA, b);                                     \
        z1[m] = fmaf(wh[1][m][3], vB, b);                                 \
    }                                                                     \
    const float igA = fmaf(0.5f, tanh_mufu(z0[0]), 0.5f);                 \
    const float fgA = fmaf(0.5f, tanh_mufu(z0[1]), 0.5f);                 \
    const float gvA = tanh_mufu(z0[2]);                                   \
    const float ogA = fmaf(0.5f, tanh_mufu(z0[3]), 0.5f);                 \
    const float CNA = fmaf(fgA, cA, igA * gvA);                           \
    const float HNA = ogA * tanh_mufu(CNA);                               \
    const float igB = fmaf(0.5f, tanh_mufu(z1[0]), 0.5f);                 \
    const float fgB = fmaf(0.5f, tanh_mufu(z1[1]), 0.5f);                 \
    const float gvB = tanh_mufu(z1[2]);                                   \
    const float ogB = fmaf(0.5f, tanh_mufu(z1[3]), 0.5f);                 \
    const float CNB = fmaf(fgB, cB, igB * gvB);                           \
    const float HNB = ogB * tanh_mufu(CNB)

#define COMMIT() { cA = cnA; hA = hnA; cB = cnB; hB = hnB; }

    // ---- warmup ----
    if (blockIdx.x == 0) {
        // masked path: dead steps + low-clamped prefetch (covers g==0)
        #pragma unroll 1
        for (int s = 0; s < WU; ++s) {
            const int t = t0 + s;
            const float4 xt = x0;
            int tn = t + PF; tn = tn < 0 ? 0 : tn;
            float4 xn = __ldg(&x[tn]);
            x0 = x1; x1 = x2; x2 = x3; x3 = xn;

            STEP(xt, cnA, hnA, cnB, hnB);
            const bool live = (t >= 0);
            cA = live ? cnA : cA;  hA = live ? hnA : hA;
            cB = live ? cnB : cB;  hB = live ? hnB : hB;
        }
    } else {
        const float4* xin = x + t0 + PF;
        #pragma unroll 1
        for (int s = 0; s < WU; s += 4) {
            { STEP(x0, cnA, hnA, cnB, hnB); COMMIT(); }  x0 = __ldg(&xin[s + 0]);
            { STEP(x1, cnA, hnA, cnB, hnB); COMMIT(); }  x1 = __ldg(&xin[s + 1]);
            { STEP(x2, cnA, hnA, cnB, hnB); COMMIT(); }  x2 = __ldg(&xin[s + 2]);
            { STEP(x3, cnA, hnA, cnB, hnB); COMMIT(); }  x3 = __ldg(&xin[s + 3]);
        }
    }

    // ---- emission: store owned element pair as one float2 per step ----
    float* op = out + (size_t)outStart * 4 + 2 * p;
    if (blockIdx.x == gridDim.x - 1) {
        #pragma unroll 1
        for (int s = WU; s < WU + CL; ++s) {
            const float4 xt = x0;
            int tn = t0 + s + PF; tn = tn >= T_LEN ? T_LEN - 1 : tn;
            float4 xn = __ldg(&x[tn]);
            x0 = x1; x1 = x2; x2 = x3; x3 = xn;

            STEP(xt, cnA, hnA, cnB, hnB); COMMIT();
            *(float2*)op = make_float2(hA, hB);
            op += 4;
        }
    } else {
        const float4* xin = x + t0 + PF;    // reaches outStart+CL+3 < T here
        #pragma unroll 1
        for (int s = WU; s < WU + CL; s += 4) {
            { STEP(x0, cnA, hnA, cnB, hnB); COMMIT();
              *(float2*)(op + 0)  = make_float2(hA, hB); }  x0 = __ldg(&xin[s + 0]);
            { STEP(x1, cnA, hnA, cnB, hnB); COMMIT();
              *(float2*)(op + 4)  = make_float2(hA, hB); }  x1 = __ldg(&xin[s + 1]);
            { STEP(x2, cnA, hnA, cnB, hnB); COMMIT();
              *(float2*)(op + 8)  = make_float2(hA, hB); }  x2 = __ldg(&xin[s + 2]);
            { STEP(x3, cnA, hnA, cnB, hnB); COMMIT();
              *(float2*)(op + 12) = make_float2(hA, hB); }  x3 = __ldg(&xin[s + 3]);
            op += 16;
        }
    }
#undef STEP
#undef COMMIT
}

extern "C" void kernel_launch(void* const* d_in, const int* in_sizes, int n_in,
                              void* d_out, int out_size)
{
    const float4*  x  = (const float4*)d_in[0];
    const float*  Wih = (const float*)d_in[1];
    const float*  Whh = (const float*)d_in[2];
    const float*  bih = (const float*)d_in[3];
    const float*  bhh = (const float*)d_in[4];
    const float*  h0  = (const float*)d_in[5];
    const float*  c0  = (const float*)d_in[6];
    float*        out = (float*)d_out;

    (void)in_sizes; (void)n_in; (void)out_size;

    lstm_chunked_scan<<<NTHREADS / BLOCK, BLOCK>>>(x, Wih, Whh, bih, bhh, h0, c0, out);
}

// round 13
// speedup vs baseline: 1.1699x; 1.1699x over previous
#include <cuda_runtime.h>

// LSTM, batch=1, H=4, T=2^20, float32.
// Chunked time-parallel scan exploiting exponential state contraction.
// R12 = R10 scalar step + block-staged x in shared memory:
//   - BLOCK=128 = 32 chunks; the block's 1056-step x window (16.9KB) is
//     preloaded coalesced ONCE, then the whole scan runs from SMEM.
//   - skewed layout slot = 33*c + s: the 8 chunk-addresses per warp-LDS
//     hit banks {0,4,..,28} -> conflict-free LDS.128 (4 wf vs 8 for the
//     old scattered LDG, latency 29 vs 234).
//   - no prefetch pipeline, no per-step clamps (preload clamps instead);
//     emission is one clean path for ALL blocks; only block 0 masks warmup.
// CL=32, WU=32, 131072 threads / 4096 warps / 1024 blocks.

#define T_LEN   1048576
#define CL      32
#define WU      32
#define NCHUNK  (T_LEN / CL)        // 32768
#define NTHREADS (NCHUNK * 4)       // 131072
#define BLOCK   128
#define CPB     (BLOCK / 4)         // 32 chunks per block
#define WIN     (CPB * CL + WU + CL)// 1056 timesteps per block window
#define XSLOTS  (WIN + WIN / 32 + 2)// skewed capacity

__device__ __forceinline__ float tanh_mufu(float z) {
    float r;
    asm("tanh.approx.f32 %0, %1;" : "=f"(r) : "f"(z));
    return r;
}
// width-4 butterfly shuffle, bare SHFL.BFLY
__device__ __forceinline__ float shfl_bfly4_1(float v) {
    float r;
    asm("shfl.sync.bfly.b32 %0, %1, 1, 0x1c1f, 0xffffffff;" : "=f"(r) : "f"(v));
    return r;
}
__device__ __forceinline__ float shfl_bfly4_2(float v) {
    float r;
    asm("shfl.sync.bfly.b32 %0, %1, 2, 0x1c1f, 0xffffffff;" : "=f"(r) : "f"(v));
    return r;
}
__device__ __forceinline__ float shfl_bfly4_3(float v) {
    float r;
    asm("shfl.sync.bfly.b32 %0, %1, 3, 0x1c1f, 0xffffffff;" : "=f"(r) : "f"(v));
    return r;
}

__global__ void __launch_bounds__(BLOCK, 7)
lstm_chunked_scan(const float4* __restrict__ x,      // [T] of float4 (H=4)
                  const float*  __restrict__ Wih,    // [16][4]
                  const float*  __restrict__ Whh,    // [16][4]
                  const float*  __restrict__ bih,    // [16]
                  const float*  __restrict__ bhh,    // [16]
                  const float*  __restrict__ h0v,    // [4]
                  const float*  __restrict__ c0v,    // [4]
                  float*        __restrict__ out)    // [T][4]
{
    __shared__ float4 xs[XSLOTS];

    const int c = threadIdx.x >> 2;              // chunk within block
    const int j = threadIdx.x & 3;               // output element
    const int g = blockIdx.x * CPB + c;          // global chunk id

    // ---- preload the block's x window (clamped, coalesced) ----
    const int t_base = blockIdx.x * (CPB * CL) - WU;
    #pragma unroll 1
    for (int i = threadIdx.x; i < WIN; i += BLOCK) {
        int t = t_base + i;
        t = t < 0 ? 0 : (t >= T_LEN ? T_LEN - 1 : t);
        xs[i + (i >> 5)] = __ldg(&x[t]);         // skew: +1 slot per 32
    }

    // Scalar per-lane weights. m: 0=i 1=f 2=g 3=o, row r=j+4m.
    // i/f/o rows prescaled by 0.5 (sigmoid(z)=0.5*tanh(z/2)+0.5; 0.5*z folded
    // into weights+bias). Whh slot k multiplies h from lane j^k (k=0: own h).
    float wx[4][4], wh[4][4], bz[4];
    #pragma unroll
    for (int m = 0; m < 4; m++) {
        const int r = j + 4 * m;
        const float sc = (m == 2) ? 1.0f : 0.5f;
        #pragma unroll
        for (int k = 0; k < 4; k++) {
            wx[m][k] = sc * __ldg(&Wih[r * 4 + k]);
            wh[m][k] = sc * __ldg(&Whh[r * 4 + (j ^ k)]);
        }
        bz[m] = sc * (__ldg(&bih[r]) + __ldg(&bhh[r]));
    }

    float h = __ldg(&h0v[j]);
    float c_ = __ldg(&c0v[j]);

    __syncthreads();

    // chunk c's window: warmup step s -> slot 33c + s   (s in [0,32))
    //                   emission step s -> slot 33c + s + 1 (s in [32,64))
    const float4* xw = &xs[33 * c];

#define STEP(XT, CN, HN)                                                  \
    const float v1 = shfl_bfly4_1(h);                                     \
    const float v2 = shfl_bfly4_2(h);                                     \
    const float v3 = shfl_bfly4_3(h);                                     \
    float z[4];                                                           \
    _Pragma("unroll")                                                     \
    for (int m = 0; m < 4; m++) {                                         \
        float a = fmaf(wx[m][0], (XT).x, bz[m]);                          \
        a = fmaf(wx[m][1], (XT).y, a);                                    \
        a = fmaf(wx[m][2], (XT).z, a);                                    \
        a = fmaf(wx[m][3], (XT).w, a);                                    \
        a = fmaf(wh[m][0], h, a);                                         \
        a = fmaf(wh[m][3], v3, a);                                        \
        a = fmaf(wh[m][2], v2, a);                                        \
        z[m] = fmaf(wh[m][1], v1, a);                                     \
    }                                                                     \
    const float ig = fmaf(0.5f, tanh_mufu(z[0]), 0.5f);                   \
    const float fg = fmaf(0.5f, tanh_mufu(z[1]), 0.5f);                   \
    const float gv = tanh_mufu(z[2]);                                     \
    const float og = fmaf(0.5f, tanh_mufu(z[3]), 0.5f);                   \
    const float CN = fmaf(fg, c_, ig * gv);                               \
    const float HN = og * tanh_mufu(CN)

    // ---- warmup (no stores) ----
    if (blockIdx.x == 0) {
        // only chunk 0 has dead steps; per-thread mask, warp stays converged
        const int t0 = g * CL - WU;
        #pragma unroll 4
        for (int s = 0; s < WU; ++s) {
            const float4 xt = xw[s];
            STEP(xt, cn, hn);
            const bool live = (t0 + s >= 0);
            c_ = live ? cn : c_;
            h  = live ? hn : h;
        }
    } else {
        #pragma unroll 4
        for (int s = 0; s < WU; ++s) {
            const float4 xt = xw[s];
            STEP(xt, cn, hn);
            c_ = cn;
            h  = hn;
        }
    }

    // ---- emission (clean path for every block; preload absorbed clamps) ----
    float* op = out + (size_t)(g * CL) * 4 + j;
    const float4* xe = xw + 1;                   // skew bump at s==32
    #pragma unroll 4
    for (int s = WU; s < WU + CL; ++s) {
        const float4 xt = xe[s];
        STEP(xt, cn, hn);
        c_ = cn;
        h  = hn;
        *op = h;
        op += 4;
    }
#undef STEP
}

extern "C" void kernel_launch(void* const* d_in, const int* in_sizes, int n_in,
                              void* d_out, int out_size)
{
    const float4*  x  = (const float4*)d_in[0];
    const float*  Wih = (const float*)d_in[1];
    const float*  Whh = (const float*)d_in[2];
    const float*  bih = (const float*)d_in[3];
    const float*  bhh = (const float*)d_in[4];
    const float*  h0  = (const float*)d_in[5];
    const float*  c0  = (const float*)d_in[6];
    float*        out = (float*)d_out;

    (void)in_sizes; (void)n_in; (void)out_size;

    lstm_chunked_scan<<<NTHREADS / BLOCK, BLOCK>>>(x, Wih, Whh, bih, bhh, h0, c0, out);
}